// round 8
// baseline (speedup 1.0000x reference)
#include <cuda_runtime.h>
#include <cuda_bf16.h>

// ---------------------------------------------------------------------------
// SAGE 2-layer GraphSAGE, mean aggregation.
//   agg1 = mean_{src->i} x[src];  h = relu(x@Ws1 + agg1@Wn1 + b1)
//   out  = h@Ws2 + mean_{src->i} (h@Wn2)[src] + b2   (aggregation is linear)
// Index dtype (int32 vs int64) detected at runtime on-device.
// RULES: never pass __device__ globals as kernel args (R5 lesson).
// ---------------------------------------------------------------------------

#define N_NODES 100000
#define N_EDGES 1600000
#define D_IN    128
#define D_HID   128
#define D_OUT   64

#define SCAN_NB ((N_NODES + 127) / 128)   // 782 blocks of 128 nodes

// -------------------- device scratch (no allocations allowed) --------------
__device__ int   g_i64;                 // 1 if edge indices are int64
__device__ int   g_deg[N_NODES];
__device__ int   g_rowptr[N_NODES + 1];
__device__ int   g_cursor[N_NODES];
__device__ int   g_bsum[SCAN_NB];
__device__ int   g_boff[SCAN_NB];
__device__ int   g_csrsrc[N_EDGES];
__device__ float g_agg[(size_t)N_NODES * D_IN];
__device__ float g_h[(size_t)N_NODES * D_HID];
__device__ float g_t[(size_t)N_NODES * D_OUT];

// -------------------- packed f32x2 helpers (Blackwell FFMA2 pipe) ----------
__device__ __forceinline__ unsigned long long pk2(float lo, float hi) {
    unsigned long long r;
    asm("mov.b64 %0, {%1, %2};" : "=l"(r) : "f"(lo), "f"(hi));
    return r;
}
__device__ __forceinline__ void fma2(unsigned long long& d,
                                     unsigned long long a,
                                     unsigned long long b) {
    asm("fma.rn.f32x2 %0, %1, %2, %0;" : "+l"(d) : "l"(a), "l"(b));
}
__device__ __forceinline__ float2 unpk2(unsigned long long v) {
    float2 r;
    asm("mov.b64 {%0, %1}, %2;" : "=f"(r.x), "=f"(r.y) : "l"(v));
    return r;
}

// -------------------- fused dtype detection + degree zero -------------------
// int64 values in [0, 2^31) have zero odd 32-bit words (little-endian).
__global__ void k_detect_zero(const void* srcbuf) {
    int i = blockIdx.x * blockDim.x + threadIdx.x;
    if (i < N_NODES) g_deg[i] = 0;
    if (blockIdx.x == 0) {
        const int* w = (const int*)srcbuf;
        __shared__ int odd_nz;
        if (threadIdx.x == 0) odd_nz = 0;
        __syncthreads();
        int bad = 0;
        for (int k = threadIdx.x; k < 1024; k += blockDim.x)
            if (w[2 * k + 1] != 0) bad = 1;       // stays within 8KB of buffer
        if (bad) atomicOr(&odd_nz, 1);
        __syncthreads();
        if (threadIdx.x == 0) g_i64 = (odd_nz == 0) ? 1 : 0;
    }
}

__device__ __forceinline__ int idx_at(const void* p, int e, int i64) {
    return i64 ? (int)((const long long*)p)[e] : ((const int*)p)[e];
}

// -------------------- CSR build ---------------------------------------------
__global__ void k_hist(const void* dst) {
    int e = blockIdx.x * blockDim.x + threadIdx.x;
    int i64 = g_i64;
    if (e < N_EDGES) {
        int d = idx_at(dst, e, i64);
        if (d >= 0 && d < N_NODES) atomicAdd(&g_deg[d], 1);
    }
}

// phase 1: per-block (128 nodes) degree sums
__global__ __launch_bounds__(128) void k_scan_partial() {
    __shared__ int s[128];
    int t = threadIdx.x;
    int i = blockIdx.x * 128 + t;
    int d = (i < N_NODES) ? g_deg[i] : 0;
    s[t] = d;
    __syncthreads();
#pragma unroll
    for (int off = 1; off < 128; off <<= 1) {
        int v = (t >= off) ? s[t - off] : 0;
        __syncthreads();
        s[t] += v;
        __syncthreads();
    }
    if (t == 127) g_bsum[blockIdx.x] = s[127];
}

// phase 2: single-block scan over SCAN_NB block totals (<=1024)
__global__ __launch_bounds__(1024) void k_scan_tops() {
    __shared__ int s[1024];
    int t = threadIdx.x;
    int v0 = (t < SCAN_NB) ? g_bsum[t] : 0;
    s[t] = v0;
    __syncthreads();
#pragma unroll
    for (int off = 1; off < 1024; off <<= 1) {
        int v = (t >= off) ? s[t - off] : 0;
        __syncthreads();
        s[t] += v;
        __syncthreads();
    }
    if (t < SCAN_NB) g_boff[t] = s[t] - v0;        // exclusive
    if (t == 1023) g_rowptr[N_NODES] = s[1023];    // grand total
}

// phase 3: rowptr/cursor fill
__global__ __launch_bounds__(128) void k_scan_fill() {
    __shared__ int s[128];
    int t = threadIdx.x;
    int i = blockIdx.x * 128 + t;
    int d = (i < N_NODES) ? g_deg[i] : 0;
    s[t] = d;
    __syncthreads();
#pragma unroll
    for (int off = 1; off < 128; off <<= 1) {
        int v = (t >= off) ? s[t - off] : 0;
        __syncthreads();
        s[t] += v;
        __syncthreads();
    }
    if (i < N_NODES) {
        int p = g_boff[blockIdx.x] + s[t] - d;     // exclusive prefix
        g_rowptr[i] = p;
        g_cursor[i] = p;
    }
}

__global__ void k_scatter(const void* src, const void* dst) {
    int e = blockIdx.x * blockDim.x + threadIdx.x;
    int i64 = g_i64;
    if (e < N_EDGES) {
        int d = idx_at(dst, e, i64);
        int s = idx_at(src, e, i64);
        if (d >= 0 && d < N_NODES && s >= 0 && s < N_NODES) {
            int pos = atomicAdd(&g_cursor[d], 1);
            g_csrsrc[pos] = s;
        }
    }
}

// -------------------- aggregation kernels ----------------------------------
// layer 1: one warp per node, 128 floats = 32 float4 lanes, 4-deep MLP
__global__ void k_agg128(const float* __restrict__ x) {
    int gtid = blockIdx.x * blockDim.x + threadIdx.x;
    int node = gtid >> 5;
    int lane = gtid & 31;
    if (node >= N_NODES) return;
    int beg = g_rowptr[node];
    int end = g_rowptr[node + 1];
    const float4* x4 = (const float4*)x;
    float4 a0 = make_float4(0.f, 0.f, 0.f, 0.f);
    float4 a1 = make_float4(0.f, 0.f, 0.f, 0.f);
    float4 a2 = make_float4(0.f, 0.f, 0.f, 0.f);
    float4 a3 = make_float4(0.f, 0.f, 0.f, 0.f);
    int j = beg;
    for (; j + 3 < end; j += 4) {
        int s0 = g_csrsrc[j];
        int s1 = g_csrsrc[j + 1];
        int s2 = g_csrsrc[j + 2];
        int s3 = g_csrsrc[j + 3];
        float4 v0 = x4[(size_t)s0 * 32 + lane];
        float4 v1 = x4[(size_t)s1 * 32 + lane];
        float4 v2 = x4[(size_t)s2 * 32 + lane];
        float4 v3 = x4[(size_t)s3 * 32 + lane];
        a0.x += v0.x; a0.y += v0.y; a0.z += v0.z; a0.w += v0.w;
        a1.x += v1.x; a1.y += v1.y; a1.z += v1.z; a1.w += v1.w;
        a2.x += v2.x; a2.y += v2.y; a2.z += v2.z; a2.w += v2.w;
        a3.x += v3.x; a3.y += v3.y; a3.z += v3.z; a3.w += v3.w;
    }
    for (; j < end; j++) {
        int s0 = g_csrsrc[j];
        float4 v0 = x4[(size_t)s0 * 32 + lane];
        a0.x += v0.x; a0.y += v0.y; a0.z += v0.z; a0.w += v0.w;
    }
    int deg = end - beg;
    float inv = 1.0f / (float)(deg > 0 ? deg : 1);
    float4 r = make_float4((a0.x + a1.x + a2.x + a3.x) * inv,
                           (a0.y + a1.y + a2.y + a3.y) * inv,
                           (a0.z + a1.z + a2.z + a3.z) * inv,
                           (a0.w + a1.w + a2.w + a3.w) * inv);
    ((float4*)g_agg)[(size_t)node * 32 + lane] = r;
}

// layer 2: one warp per node over g_t (64 floats = 32 float2 lanes), 4-deep MLP
__global__ void k_agg64(float* __restrict__ out) {
    int gtid = blockIdx.x * blockDim.x + threadIdx.x;
    int node = gtid >> 5;
    int lane = gtid & 31;
    if (node >= N_NODES) return;
    int beg = g_rowptr[node];
    int end = g_rowptr[node + 1];
    const float2* t2 = (const float2*)g_t;
    float2 a0 = make_float2(0.f, 0.f);
    float2 a1 = make_float2(0.f, 0.f);
    float2 a2 = make_float2(0.f, 0.f);
    float2 a3 = make_float2(0.f, 0.f);
    int j = beg;
    for (; j + 3 < end; j += 4) {
        int s0 = g_csrsrc[j];
        int s1 = g_csrsrc[j + 1];
        int s2 = g_csrsrc[j + 2];
        int s3 = g_csrsrc[j + 3];
        float2 v0 = t2[(size_t)s0 * 32 + lane];
        float2 v1 = t2[(size_t)s1 * 32 + lane];
        float2 v2 = t2[(size_t)s2 * 32 + lane];
        float2 v3 = t2[(size_t)s3 * 32 + lane];
        a0.x += v0.x; a0.y += v0.y;
        a1.x += v1.x; a1.y += v1.y;
        a2.x += v2.x; a2.y += v2.y;
        a3.x += v3.x; a3.y += v3.y;
    }
    for (; j < end; j++) {
        int s0 = g_csrsrc[j];
        float2 v0 = t2[(size_t)s0 * 32 + lane];
        a0.x += v0.x; a0.y += v0.y;
    }
    int deg = end - beg;
    float inv = 1.0f / (float)(deg > 0 ? deg : 1);
    float2* o2 = (float2*)out;
    float2 cur = o2[(size_t)node * 32 + lane];
    cur.x += (a0.x + a1.x + a2.x + a3.x) * inv;
    cur.y += (a0.y + a1.y + a2.y + a3.y) * inv;
    o2[(size_t)node * 32 + lane] = cur;
}

// -------------------- GEMM kernels (pipelined, f32x2 FMA) ------------------
#define BM 128
#define BN 128
#define BK 16
#define TM 8
#define TN 8

// g_h = relu( x @ Ws1 + g_agg @ Wn1 + b1 ) : M=100000, N=128, K=256 ([x|agg])
__global__ __launch_bounds__(256) void k_gemm1(
    const float* __restrict__ x, const float* __restrict__ Ws,
    const float* __restrict__ Wn, const float* __restrict__ bias) {
    __shared__ __align__(16) float As[BK][BM + 4];
    __shared__ __align__(16) float Bs[BK][BN];
    const int tid = threadIdx.x;
    const int tx = tid & 15;          // N direction (8 cols each)
    const int ty = tid >> 4;          // M direction (8 rows each)
    const int rowBase = blockIdx.x * BM;
    const int aRow = tid >> 1;
    const int aCol = (tid & 1) * 8;
    const int bRow = tid >> 4;        // 0..15
    const int bCol = (tid & 15) * 8;  // 0..120

    unsigned long long acc[TM][TN / 2];
#pragma unroll
    for (int i = 0; i < TM; i++)
#pragma unroll
        for (int j = 0; j < TN / 2; j++) acc[i][j] = 0ull;

    int arow_g = rowBase + aRow;
    if (arow_g >= N_NODES) arow_g = N_NODES - 1;

    // prefetch kk = 0
    float4 a0, a1, b0, b1v;
    {
        const float* Aptr = x + (size_t)arow_g * D_IN + aCol;
        a0 = *(const float4*)(Aptr);
        a1 = *(const float4*)(Aptr + 4);
        const float* Bptr = Ws + bRow * 128 + bCol;
        b0 = *(const float4*)(Bptr);
        b1v = *(const float4*)(Bptr + 4);
    }

    for (int kk = 0; kk < 16; ++kk) {
        __syncthreads();
        As[aCol + 0][aRow] = a0.x; As[aCol + 1][aRow] = a0.y;
        As[aCol + 2][aRow] = a0.z; As[aCol + 3][aRow] = a0.w;
        As[aCol + 4][aRow] = a1.x; As[aCol + 5][aRow] = a1.y;
        As[aCol + 6][aRow] = a1.z; As[aCol + 7][aRow] = a1.w;
        *(float4*)&Bs[bRow][bCol] = b0;
        *(float4*)&Bs[bRow][bCol + 4] = b1v;
        // prefetch kk+1 (retires under the math below)
        if (kk + 1 < 16) {
            int kn = kk + 1;
            const float* Aptr = (kn < 8)
                ? (x     + (size_t)arow_g * D_IN + kn * 16 + aCol)
                : (g_agg + (size_t)arow_g * D_IN + (kn - 8) * 16 + aCol);
            a0 = *(const float4*)(Aptr);
            a1 = *(const float4*)(Aptr + 4);
            int kg = kn * 16 + bRow;  // 0..255
            const float* Bptr = (kg < 128) ? (Ws + kg * 128 + bCol)
                                           : (Wn + (kg - 128) * 128 + bCol);
            b0 = *(const float4*)(Bptr);
            b1v = *(const float4*)(Bptr + 4);
        }
        __syncthreads();

#pragma unroll
        for (int k = 0; k < BK; k++) {
            float a[8], b[8];
            *(float4*)&a[0] = *(const float4*)&As[k][ty * TM];
            *(float4*)&a[4] = *(const float4*)&As[k][ty * TM + 4];
            *(float4*)&b[0] = *(const float4*)&Bs[k][tx * TN];
            *(float4*)&b[4] = *(const float4*)&Bs[k][tx * TN + 4];
            unsigned long long bb[4] = {pk2(b[0], b[1]), pk2(b[2], b[3]),
                                        pk2(b[4], b[5]), pk2(b[6], b[7])};
#pragma unroll
            for (int i = 0; i < 8; i++) {
                unsigned long long a2 = pk2(a[i], a[i]);
#pragma unroll
                for (int j = 0; j < 4; j++) fma2(acc[i][j], a2, bb[j]);
            }
        }
    }

    float bloc[8];
#pragma unroll
    for (int j = 0; j < 8; j++) bloc[j] = bias[tx * TN + j];
#pragma unroll
    for (int i = 0; i < TM; i++) {
        int r = rowBase + ty * TM + i;
        if (r < N_NODES) {
            float v[8];
#pragma unroll
            for (int j = 0; j < 4; j++) {
                float2 p = unpk2(acc[i][j]);
                v[2 * j] = p.x; v[2 * j + 1] = p.y;
            }
#pragma unroll
            for (int j = 0; j < 8; j++) {
                float z = v[j] + bloc[j];
                v[j] = z > 0.f ? z : 0.f;
            }
            float4* dst4 = (float4*)(g_h + (size_t)r * D_HID + tx * TN);
            dst4[0] = make_float4(v[0], v[1], v[2], v[3]);
            dst4[1] = make_float4(v[4], v[5], v[6], v[7]);
        }
    }
}

// [self | neigh] = g_h @ [Ws2 | Wn2] : M=100000, N=128 (64+64), K=128
__global__ __launch_bounds__(256) void k_gemm2(
    const float* __restrict__ Ws2, const float* __restrict__ Wn2,
    const float* __restrict__ bias, float* __restrict__ out) {
    __shared__ __align__(16) float As[BK][BM + 4];
    __shared__ __align__(16) float Bs[BK][BN];
    const int tid = threadIdx.x;
    const int tx = tid & 15;
    const int ty = tid >> 4;
    const int rowBase = blockIdx.x * BM;
    const int aRow = tid >> 1;
    const int aCol = (tid & 1) * 8;
    const int bRow = tid >> 4;
    const int bCol = (tid & 15) * 8;

    unsigned long long acc[TM][TN / 2];
#pragma unroll
    for (int i = 0; i < TM; i++)
#pragma unroll
        for (int j = 0; j < TN / 2; j++) acc[i][j] = 0ull;

    int arow_g = rowBase + aRow;
    if (arow_g >= N_NODES) arow_g = N_NODES - 1;

    // prefetch kk = 0
    float4 a0, a1, b0, b1v;
    {
        const float* Aptr = g_h + (size_t)arow_g * D_HID + aCol;
        a0 = *(const float4*)(Aptr);
        a1 = *(const float4*)(Aptr + 4);
        const float* Bptr = (bCol < 64) ? (Ws2 + bRow * 64 + bCol)
                                        : (Wn2 + bRow * 64 + (bCol - 64));
        b0 = *(const float4*)(Bptr);
        b1v = *(const float4*)(Bptr + 4);
    }

    for (int kk = 0; kk < 8; ++kk) {
        __syncthreads();
        As[aCol + 0][aRow] = a0.x; As[aCol + 1][aRow] = a0.y;
        As[aCol + 2][aRow] = a0.z; As[aCol + 3][aRow] = a0.w;
        As[aCol + 4][aRow] = a1.x; As[aCol + 5][aRow] = a1.y;
        As[aCol + 6][aRow] = a1.z; As[aCol + 7][aRow] = a1.w;
        *(float4*)&Bs[bRow][bCol] = b0;
        *(float4*)&Bs[bRow][bCol + 4] = b1v;
        if (kk + 1 < 8) {
            int kn = kk + 1;
            const float* Aptr = g_h + (size_t)arow_g * D_HID + kn * 16 + aCol;
            a0 = *(const float4*)(Aptr);
            a1 = *(const float4*)(Aptr + 4);
            int kg = kn * 16 + bRow;  // 0..127
            const float* Bptr = (bCol < 64) ? (Ws2 + kg * 64 + bCol)
                                            : (Wn2 + kg * 64 + (bCol - 64));
            b0 = *(const float4*)(Bptr);
            b1v = *(const float4*)(Bptr + 4);
        }
        __syncthreads();

#pragma unroll
        for (int k = 0; k < BK; k++) {
            float a[8], b[8];
            *(float4*)&a[0] = *(const float4*)&As[k][ty * TM];
            *(float4*)&a[4] = *(const float4*)&As[k][ty * TM + 4];
            *(float4*)&b[0] = *(const float4*)&Bs[k][tx * TN];
            *(float4*)&b[4] = *(const float4*)&Bs[k][tx * TN + 4];
            unsigned long long bb[4] = {pk2(b[0], b[1]), pk2(b[2], b[3]),
                                        pk2(b[4], b[5]), pk2(b[6], b[7])};
#pragma unroll
            for (int i = 0; i < 8; i++) {
                unsigned long long a2 = pk2(a[i], a[i]);
#pragma unroll
                for (int j = 0; j < 4; j++) fma2(acc[i][j], a2, bb[j]);
            }
        }
    }

    const bool selfHalf = (tx < 8);
    float bloc[8];
#pragma unroll
    for (int j = 0; j < 8; j++) bloc[j] = selfHalf ? bias[tx * TN + j] : 0.f;
#pragma unroll
    for (int i = 0; i < TM; i++) {
        int r = rowBase + ty * TM + i;
        if (r < N_NODES) {
            float v[8];
#pragma unroll
            for (int j = 0; j < 4; j++) {
                float2 p = unpk2(acc[i][j]);
                v[2 * j] = p.x; v[2 * j + 1] = p.y;
            }
#pragma unroll
            for (int j = 0; j < 8; j++) v[j] += bloc[j];
            float4* dst4 = selfHalf
                ? (float4*)(out + (size_t)r * D_OUT + tx * TN)
                : (float4*)(g_t + (size_t)r * D_OUT + (tx - 8) * TN);
            dst4[0] = make_float4(v[0], v[1], v[2], v[3]);
            dst4[1] = make_float4(v[4], v[5], v[6], v[7]);
        }
    }
}

// ---------------------------------------------------------------------------
extern "C" void kernel_launch(void* const* d_in, const int* in_sizes, int n_in,
                              void* d_out, int out_size) {
    const float* x   = (const float*)d_in[0];
    const void*  src = d_in[1];
    const void*  dst = d_in[2];
    const float* Ws1 = (const float*)d_in[3];
    const float* Wn1 = (const float*)d_in[4];
    const float* b1  = (const float*)d_in[5];
    const float* Ws2 = (const float*)d_in[6];
    const float* Wn2 = (const float*)d_in[7];
    const float* b2  = (const float*)d_in[8];
    float* out = (float*)d_out;

    // 1) CSR build (detect dtype + zero degrees fused)
    k_detect_zero<<<(N_NODES + 255) / 256, 256>>>(src);
    k_hist<<<(N_EDGES + 255) / 256, 256>>>(dst);
    k_scan_partial<<<SCAN_NB, 128>>>();
    k_scan_tops<<<1, 1024>>>();
    k_scan_fill<<<SCAN_NB, 128>>>();
    k_scatter<<<(N_EDGES + 255) / 256, 256>>>(src, dst);

    // 2) layer 1
    k_agg128<<<(N_NODES * 32 + 255) / 256, 256>>>(x);
    k_gemm1<<<(N_NODES + BM - 1) / BM, 256>>>(x, Ws1, Wn1, b1);

    // 3) layer 2 (transform first, aggregate 64-wide afterwards)
    k_gemm2<<<(N_NODES + BM - 1) / BM, 256>>>(Ws2, Wn2, b2, out);
    k_agg64<<<(N_NODES * 32 + 255) / 256, 256>>>(out);
}

// round 9
// speedup vs baseline: 1.0645x; 1.0645x over previous
#include <cuda_runtime.h>
#include <cuda_bf16.h>
#include <cuda_fp16.h>

// ---------------------------------------------------------------------------
// SAGE 2-layer GraphSAGE, mean aggregation.
//   agg1 = mean_{src->i} x[src];  h = relu(x@Ws1 + agg1@Wn1 + b1)
//   out  = h@Ws2 + mean_{src->i} (h@Wn2)[src] + b2   (aggregation is linear)
// fp16 gather payloads (fp32 accumulation): halves aggregation traffic.
// RULES: never pass __device__ globals as kernel args (R5 lesson).
// ---------------------------------------------------------------------------

#define N_NODES 100000
#define N_EDGES 1600000
#define D_IN    128
#define D_HID   128
#define D_OUT   64

#define SCAN_NB ((N_NODES + 127) / 128)   // 782 blocks of 128 nodes

// -------------------- device scratch (no allocations allowed) --------------
__device__ int    g_i64;                // 1 if edge indices are int64
__device__ int    g_deg[N_NODES];
__device__ int    g_rowptr[N_NODES + 1];
__device__ int    g_cursor[N_NODES];
__device__ int    g_bsum[SCAN_NB];
__device__ int    g_boff[SCAN_NB];
__device__ int    g_csrsrc[N_EDGES];
__device__ __half g_xh[(size_t)N_NODES * D_IN];   // fp16 copy of x
__device__ float  g_agg[(size_t)N_NODES * D_IN];
__device__ float  g_h[(size_t)N_NODES * D_HID];
__device__ __half g_th[(size_t)N_NODES * D_OUT];  // h @ W_neigh2, fp16

// -------------------- packed f32x2 helpers (Blackwell FFMA2 pipe) ----------
__device__ __forceinline__ unsigned long long pk2(float lo, float hi) {
    unsigned long long r;
    asm("mov.b64 %0, {%1, %2};" : "=l"(r) : "f"(lo), "f"(hi));
    return r;
}
__device__ __forceinline__ void fma2(unsigned long long& d,
                                     unsigned long long a,
                                     unsigned long long b) {
    asm("fma.rn.f32x2 %0, %1, %2, %0;" : "+l"(d) : "l"(a), "l"(b));
}
__device__ __forceinline__ float2 unpk2(unsigned long long v) {
    float2 r;
    asm("mov.b64 {%0, %1}, %2;" : "=f"(r.x), "=f"(r.y) : "l"(v));
    return r;
}

// -------------------- fused dtype detection + degree zero -------------------
// int64 values in [0, 2^31) have zero odd 32-bit words (little-endian).
__global__ void k_detect_zero(const void* srcbuf) {
    int i = blockIdx.x * blockDim.x + threadIdx.x;
    if (i < N_NODES) g_deg[i] = 0;
    if (blockIdx.x == 0) {
        const int* w = (const int*)srcbuf;
        __shared__ int odd_nz;
        if (threadIdx.x == 0) odd_nz = 0;
        __syncthreads();
        int bad = 0;
        for (int k = threadIdx.x; k < 1024; k += blockDim.x)
            if (w[2 * k + 1] != 0) bad = 1;       // stays within 8KB of buffer
        if (bad) atomicOr(&odd_nz, 1);
        __syncthreads();
        if (threadIdx.x == 0) g_i64 = (odd_nz == 0) ? 1 : 0;
    }
}

__device__ __forceinline__ int idx_at(const void* p, int e, int i64) {
    return i64 ? (int)((const long long*)p)[e] : ((const int*)p)[e];
}

// -------------------- x -> fp16 conversion ----------------------------------
__global__ void k_xtoh(const float* __restrict__ x) {
    int i = blockIdx.x * blockDim.x + threadIdx.x;   // one float4 per thread
    if (i < N_NODES * D_IN / 4) {
        float4 v = ((const float4*)x)[i];
        __half2 a = __floats2half2_rn(v.x, v.y);
        __half2 b = __floats2half2_rn(v.z, v.w);
        uint2 u;
        u.x = *reinterpret_cast<unsigned*>(&a);
        u.y = *reinterpret_cast<unsigned*>(&b);
        ((uint2*)g_xh)[i] = u;
    }
}

// -------------------- CSR build ---------------------------------------------
__global__ void k_hist(const void* dst) {
    int e = blockIdx.x * blockDim.x + threadIdx.x;
    int i64 = g_i64;
    if (e < N_EDGES) {
        int d = idx_at(dst, e, i64);
        if (d >= 0 && d < N_NODES) atomicAdd(&g_deg[d], 1);
    }
}

__global__ __launch_bounds__(128) void k_scan_partial() {
    __shared__ int s[128];
    int t = threadIdx.x;
    int i = blockIdx.x * 128 + t;
    int d = (i < N_NODES) ? g_deg[i] : 0;
    s[t] = d;
    __syncthreads();
#pragma unroll
    for (int off = 1; off < 128; off <<= 1) {
        int v = (t >= off) ? s[t - off] : 0;
        __syncthreads();
        s[t] += v;
        __syncthreads();
    }
    if (t == 127) g_bsum[blockIdx.x] = s[127];
}

__global__ __launch_bounds__(1024) void k_scan_tops() {
    __shared__ int s[1024];
    int t = threadIdx.x;
    int v0 = (t < SCAN_NB) ? g_bsum[t] : 0;
    s[t] = v0;
    __syncthreads();
#pragma unroll
    for (int off = 1; off < 1024; off <<= 1) {
        int v = (t >= off) ? s[t - off] : 0;
        __syncthreads();
        s[t] += v;
        __syncthreads();
    }
    if (t < SCAN_NB) g_boff[t] = s[t] - v0;        // exclusive
    if (t == 1023) g_rowptr[N_NODES] = s[1023];    // grand total
}

__global__ __launch_bounds__(128) void k_scan_fill() {
    __shared__ int s[128];
    int t = threadIdx.x;
    int i = blockIdx.x * 128 + t;
    int d = (i < N_NODES) ? g_deg[i] : 0;
    s[t] = d;
    __syncthreads();
#pragma unroll
    for (int off = 1; off < 128; off <<= 1) {
        int v = (t >= off) ? s[t - off] : 0;
        __syncthreads();
        s[t] += v;
        __syncthreads();
    }
    if (i < N_NODES) {
        int p = g_boff[blockIdx.x] + s[t] - d;     // exclusive prefix
        g_rowptr[i] = p;
        g_cursor[i] = p;
    }
}

__global__ void k_scatter(const void* src, const void* dst) {
    int e = blockIdx.x * blockDim.x + threadIdx.x;
    int i64 = g_i64;
    if (e < N_EDGES) {
        int d = idx_at(dst, e, i64);
        int s = idx_at(src, e, i64);
        if (d >= 0 && d < N_NODES && s >= 0 && s < N_NODES) {
            int pos = atomicAdd(&g_cursor[d], 1);
            g_csrsrc[pos] = s;
        }
    }
}

// -------------------- aggregation kernels (fp16 payload, fp32 accum) --------
// layer 1: one warp per node; row = 128 halfs = 32 uint2 lanes (8B/lane)
__global__ void k_agg128h() {
    int gtid = blockIdx.x * blockDim.x + threadIdx.x;
    int node = gtid >> 5;
    int lane = gtid & 31;
    if (node >= N_NODES) return;
    int beg = g_rowptr[node];
    int end = g_rowptr[node + 1];
    const uint2* xh = (const uint2*)g_xh;
    float ax0 = 0.f, ay0 = 0.f, az0 = 0.f, aw0 = 0.f;
    float ax1 = 0.f, ay1 = 0.f, az1 = 0.f, aw1 = 0.f;
    int j = beg;
    for (; j + 1 < end; j += 2) {
        int s0 = g_csrsrc[j];
        int s1 = g_csrsrc[j + 1];
        uint2 u0 = xh[(size_t)s0 * 32 + lane];
        uint2 u1 = xh[(size_t)s1 * 32 + lane];
        float2 l0 = __half22float2(*reinterpret_cast<__half2*>(&u0.x));
        float2 h0 = __half22float2(*reinterpret_cast<__half2*>(&u0.y));
        float2 l1 = __half22float2(*reinterpret_cast<__half2*>(&u1.x));
        float2 h1 = __half22float2(*reinterpret_cast<__half2*>(&u1.y));
        ax0 += l0.x; ay0 += l0.y; az0 += h0.x; aw0 += h0.y;
        ax1 += l1.x; ay1 += l1.y; az1 += h1.x; aw1 += h1.y;
    }
    if (j < end) {
        int s0 = g_csrsrc[j];
        uint2 u0 = xh[(size_t)s0 * 32 + lane];
        float2 l0 = __half22float2(*reinterpret_cast<__half2*>(&u0.x));
        float2 h0 = __half22float2(*reinterpret_cast<__half2*>(&u0.y));
        ax0 += l0.x; ay0 += l0.y; az0 += h0.x; aw0 += h0.y;
    }
    int deg = end - beg;
    float inv = 1.0f / (float)(deg > 0 ? deg : 1);
    float4 r = make_float4((ax0 + ax1) * inv, (ay0 + ay1) * inv,
                           (az0 + az1) * inv, (aw0 + aw1) * inv);
    ((float4*)g_agg)[(size_t)node * 32 + lane] = r;   // halfs 4*lane..4*lane+3
}

// layer 2: one warp per node over g_th; row = 64 halfs = 32 half2 lanes
__global__ void k_agg64h(float* __restrict__ out) {
    int gtid = blockIdx.x * blockDim.x + threadIdx.x;
    int node = gtid >> 5;
    int lane = gtid & 31;
    if (node >= N_NODES) return;
    int beg = g_rowptr[node];
    int end = g_rowptr[node + 1];
    const __half2* th = (const __half2*)g_th;
    float ax0 = 0.f, ay0 = 0.f, ax1 = 0.f, ay1 = 0.f;
    int j = beg;
    for (; j + 1 < end; j += 2) {
        int s0 = g_csrsrc[j];
        int s1 = g_csrsrc[j + 1];
        float2 v0 = __half22float2(th[(size_t)s0 * 32 + lane]);
        float2 v1 = __half22float2(th[(size_t)s1 * 32 + lane]);
        ax0 += v0.x; ay0 += v0.y;
        ax1 += v1.x; ay1 += v1.y;
    }
    if (j < end) {
        int s0 = g_csrsrc[j];
        float2 v0 = __half22float2(th[(size_t)s0 * 32 + lane]);
        ax0 += v0.x; ay0 += v0.y;
    }
    int deg = end - beg;
    float inv = 1.0f / (float)(deg > 0 ? deg : 1);
    float2* o2 = (float2*)out;
    float2 cur = o2[(size_t)node * 32 + lane];
    cur.x += (ax0 + ax1) * inv;
    cur.y += (ay0 + ay1) * inv;
    o2[(size_t)node * 32 + lane] = cur;
}

// -------------------- GEMM kernels (register-tiled, f32x2 FMA) -------------
#define BM 128
#define BN 128
#define BK 16
#define TM 8
#define TN 8

// g_h = relu( x @ Ws1 + g_agg @ Wn1 + b1 ) : M=100000, N=128, K=256 ([x|agg])
__global__ __launch_bounds__(256) void k_gemm1(
    const float* __restrict__ x, const float* __restrict__ Ws,
    const float* __restrict__ Wn, const float* __restrict__ bias) {
    __shared__ __align__(16) float As[BK][BM + 4];
    __shared__ __align__(16) float Bs[BK][BN];
    const int tid = threadIdx.x;
    const int tx = tid & 15;          // N direction (8 cols each)
    const int ty = tid >> 4;          // M direction (8 rows each)
    const int rowBase = blockIdx.x * BM;
    const int aRow = tid >> 1;
    const int aCol = (tid & 1) * 8;
    const int bRow = tid >> 4;        // 0..15
    const int bCol = (tid & 15) * 8;  // 0..120

    unsigned long long acc[TM][TN / 2];
#pragma unroll
    for (int i = 0; i < TM; i++)
#pragma unroll
        for (int j = 0; j < TN / 2; j++) acc[i][j] = 0ull;

    int arow_g = rowBase + aRow;
    if (arow_g >= N_NODES) arow_g = N_NODES - 1;

    for (int kk = 0; kk < 16; ++kk) {
        const float* Aptr = (kk < 8)
            ? (x     + (size_t)arow_g * D_IN + kk * 16 + aCol)
            : (g_agg + (size_t)arow_g * D_IN + (kk - 8) * 16 + aCol);
        float4 a0 = *(const float4*)(Aptr);
        float4 a1 = *(const float4*)(Aptr + 4);
        int kg = kk * 16 + bRow;  // 0..255
        const float* Bptr = (kg < 128) ? (Ws + kg * 128 + bCol)
                                       : (Wn + (kg - 128) * 128 + bCol);
        float4 b0 = *(const float4*)(Bptr);
        float4 b1v = *(const float4*)(Bptr + 4);

        __syncthreads();
        As[aCol + 0][aRow] = a0.x; As[aCol + 1][aRow] = a0.y;
        As[aCol + 2][aRow] = a0.z; As[aCol + 3][aRow] = a0.w;
        As[aCol + 4][aRow] = a1.x; As[aCol + 5][aRow] = a1.y;
        As[aCol + 6][aRow] = a1.z; As[aCol + 7][aRow] = a1.w;
        *(float4*)&Bs[bRow][bCol] = b0;
        *(float4*)&Bs[bRow][bCol + 4] = b1v;
        __syncthreads();

#pragma unroll
        for (int k = 0; k < BK; k++) {
            float a[8], b[8];
            *(float4*)&a[0] = *(const float4*)&As[k][ty * TM];
            *(float4*)&a[4] = *(const float4*)&As[k][ty * TM + 4];
            *(float4*)&b[0] = *(const float4*)&Bs[k][tx * TN];
            *(float4*)&b[4] = *(const float4*)&Bs[k][tx * TN + 4];
            unsigned long long bb[4] = {pk2(b[0], b[1]), pk2(b[2], b[3]),
                                        pk2(b[4], b[5]), pk2(b[6], b[7])};
#pragma unroll
            for (int i = 0; i < 8; i++) {
                unsigned long long a2 = pk2(a[i], a[i]);
#pragma unroll
                for (int j = 0; j < 4; j++) fma2(acc[i][j], a2, bb[j]);
            }
        }
    }

    float bloc[8];
#pragma unroll
    for (int j = 0; j < 8; j++) bloc[j] = bias[tx * TN + j];
#pragma unroll
    for (int i = 0; i < TM; i++) {
        int r = rowBase + ty * TM + i;
        if (r < N_NODES) {
            float v[8];
#pragma unroll
            for (int j = 0; j < 4; j++) {
                float2 p = unpk2(acc[i][j]);
                v[2 * j] = p.x; v[2 * j + 1] = p.y;
            }
#pragma unroll
            for (int j = 0; j < 8; j++) {
                float z = v[j] + bloc[j];
                v[j] = z > 0.f ? z : 0.f;
            }
            float4* dst4 = (float4*)(g_h + (size_t)r * D_HID + tx * TN);
            dst4[0] = make_float4(v[0], v[1], v[2], v[3]);
            dst4[1] = make_float4(v[4], v[5], v[6], v[7]);
        }
    }
}

// [self | neigh] = g_h @ [Ws2 | Wn2] : M=100000, N=128 (64+64), K=128
// self half (+b2) -> out fp32 ; neigh half -> g_th fp16
__global__ __launch_bounds__(256) void k_gemm2(
    const float* __restrict__ Ws2, const float* __restrict__ Wn2,
    const float* __restrict__ bias, float* __restrict__ out) {
    __shared__ __align__(16) float As[BK][BM + 4];
    __shared__ __align__(16) float Bs[BK][BN];
    const int tid = threadIdx.x;
    const int tx = tid & 15;
    const int ty = tid >> 4;
    const int rowBase = blockIdx.x * BM;
    const int aRow = tid >> 1;
    const int aCol = (tid & 1) * 8;
    const int bRow = tid >> 4;
    const int bCol = (tid & 15) * 8;

    unsigned long long acc[TM][TN / 2];
#pragma unroll
    for (int i = 0; i < TM; i++)
#pragma unroll
        for (int j = 0; j < TN / 2; j++) acc[i][j] = 0ull;

    int arow_g = rowBase + aRow;
    if (arow_g >= N_NODES) arow_g = N_NODES - 1;

    for (int kk = 0; kk < 8; ++kk) {
        const float* Aptr = g_h + (size_t)arow_g * D_HID + kk * 16 + aCol;
        float4 a0 = *(const float4*)(Aptr);
        float4 a1 = *(const float4*)(Aptr + 4);
        int kg = kk * 16 + bRow;  // 0..127
        const float* Bptr = (bCol < 64) ? (Ws2 + kg * 64 + bCol)
                                        : (Wn2 + kg * 64 + (bCol - 64));
        float4 b0 = *(const float4*)(Bptr);
        float4 b1v = *(const float4*)(Bptr + 4);

        __syncthreads();
        As[aCol + 0][aRow] = a0.x; As[aCol + 1][aRow] = a0.y;
        As[aCol + 2][aRow] = a0.z; As[aCol + 3][aRow] = a0.w;
        As[aCol + 4][aRow] = a1.x; As[aCol + 5][aRow] = a1.y;
        As[aCol + 6][aRow] = a1.z; As[aCol + 7][aRow] = a1.w;
        *(float4*)&Bs[bRow][bCol] = b0;
        *(float4*)&Bs[bRow][bCol + 4] = b1v;
        __syncthreads();

#pragma unroll
        for (int k = 0; k < BK; k++) {
            float a[8], b[8];
            *(float4*)&a[0] = *(const float4*)&As[k][ty * TM];
            *(float4*)&a[4] = *(const float4*)&As[k][ty * TM + 4];
            *(float4*)&b[0] = *(const float4*)&Bs[k][tx * TN];
            *(float4*)&b[4] = *(const float4*)&Bs[k][tx * TN + 4];
            unsigned long long bb[4] = {pk2(b[0], b[1]), pk2(b[2], b[3]),
                                        pk2(b[4], b[5]), pk2(b[6], b[7])};
#pragma unroll
            for (int i = 0; i < 8; i++) {
                unsigned long long a2 = pk2(a[i], a[i]);
#pragma unroll
                for (int j = 0; j < 4; j++) fma2(acc[i][j], a2, bb[j]);
            }
        }
    }

    const bool selfHalf = (tx < 8);
    float bloc[8];
#pragma unroll
    for (int j = 0; j < 8; j++) bloc[j] = selfHalf ? bias[tx * TN + j] : 0.f;
#pragma unroll
    for (int i = 0; i < TM; i++) {
        int r = rowBase + ty * TM + i;
        if (r < N_NODES) {
            float v[8];
#pragma unroll
            for (int j = 0; j < 4; j++) {
                float2 p = unpk2(acc[i][j]);
                v[2 * j] = p.x; v[2 * j + 1] = p.y;
            }
#pragma unroll
            for (int j = 0; j < 8; j++) v[j] += bloc[j];
            if (selfHalf) {
                float4* dst4 = (float4*)(out + (size_t)r * D_OUT + tx * TN);
                dst4[0] = make_float4(v[0], v[1], v[2], v[3]);
                dst4[1] = make_float4(v[4], v[5], v[6], v[7]);
            } else {
                __half2 p0 = __floats2half2_rn(v[0], v[1]);
                __half2 p1 = __floats2half2_rn(v[2], v[3]);
                __half2 p2 = __floats2half2_rn(v[4], v[5]);
                __half2 p3 = __floats2half2_rn(v[6], v[7]);
                uint4 u;
                u.x = *reinterpret_cast<unsigned*>(&p0);
                u.y = *reinterpret_cast<unsigned*>(&p1);
                u.z = *reinterpret_cast<unsigned*>(&p2);
                u.w = *reinterpret_cast<unsigned*>(&p3);
                *(uint4*)(g_th + (size_t)r * D_OUT + (tx - 8) * TN) = u;
            }
        }
    }
}

// ---------------------------------------------------------------------------
extern "C" void kernel_launch(void* const* d_in, const int* in_sizes, int n_in,
                              void* d_out, int out_size) {
    const float* x   = (const float*)d_in[0];
    const void*  src = d_in[1];
    const void*  dst = d_in[2];
    const float* Ws1 = (const float*)d_in[3];
    const float* Wn1 = (const float*)d_in[4];
    const float* b1  = (const float*)d_in[5];
    const float* Ws2 = (const float*)d_in[6];
    const float* Wn2 = (const float*)d_in[7];
    const float* b2  = (const float*)d_in[8];
    float* out = (float*)d_out;

    // 1) CSR build (detect dtype + zero degrees fused) and fp16 snapshot of x
    k_detect_zero<<<(N_NODES + 255) / 256, 256>>>(src);
    k_xtoh<<<(N_NODES * D_IN / 4 + 255) / 256, 256>>>(x);
    k_hist<<<(N_EDGES + 255) / 256, 256>>>(dst);
    k_scan_partial<<<SCAN_NB, 128>>>();
    k_scan_tops<<<1, 1024>>>();
    k_scan_fill<<<SCAN_NB, 128>>>();
    k_scatter<<<(N_EDGES + 255) / 256, 256>>>(src, dst);

    // 2) layer 1
    k_agg128h<<<(N_NODES * 32 + 255) / 256, 256>>>();
    k_gemm1<<<(N_NODES + BM - 1) / BM, 256>>>(x, Ws1, Wn1, b1);

    // 3) layer 2 (transform first, aggregate fp16 64-wide afterwards)
    k_gemm2<<<(N_NODES + BM - 1) / BM, 256>>>(Ws2, Wn2, b2, out);
    k_agg64h<<<(N_NODES * 32 + 255) / 256, 256>>>(out);
}

// round 10
// speedup vs baseline: 1.5020x; 1.4110x over previous
#include <cuda_runtime.h>
#include <cuda_bf16.h>
#include <cuda_fp16.h>
#include <mma.h>

using namespace nvcuda;

// ---------------------------------------------------------------------------
// SAGE 2-layer GraphSAGE, mean aggregation.
//   agg1 = mean_{src->i} x[src];  h = relu(x@Ws1 + agg1@Wn1 + b1)
//   out  = h@Ws2 + mean_{src->i} (h@Wn2)[src] + b2   (aggregation is linear)
// fp16 data path (fp32 accumulation everywhere), wmma tensor-core GEMMs.
// RULES: never pass __device__ globals as kernel args (R5 lesson).
// ---------------------------------------------------------------------------

#define N_NODES 100000
#define N_EDGES 1600000
#define D_IN    128
#define D_HID   128
#define D_OUT   64

#define SCAN_NB ((N_NODES + 127) / 128)   // 782 blocks of 128 nodes

// -------------------- device scratch (no allocations allowed) --------------
__device__ int    g_i64;                // 1 if edge indices are int64
__device__ int    g_deg[N_NODES];
__device__ int    g_rowptr[N_NODES + 1];
__device__ int    g_cursor[N_NODES];
__device__ int    g_bsum[SCAN_NB];
__device__ int    g_boff[SCAN_NB];
__device__ int    g_csrsrc[N_EDGES];
__device__ __half g_xh[(size_t)N_NODES * D_IN];    // fp16 copy of x
__device__ __half g_aggh[(size_t)N_NODES * D_IN];  // fp16 layer-1 mean
__device__ __half g_hh[(size_t)N_NODES * D_HID];   // fp16 hidden
__device__ __half g_th[(size_t)N_NODES * D_OUT];   // h @ W_neigh2, fp16
__device__ __half g_B1h[256 * 128];                // [Ws1 ; Wn1] K-major
__device__ __half g_B2h[128 * 128];                // [Ws2 | Wn2] K-major

// -------------------- fused dtype detection + degree zero -------------------
// int64 values in [0, 2^31) have zero odd 32-bit words (little-endian).
__global__ void k_detect_zero(const void* srcbuf) {
    int i = blockIdx.x * blockDim.x + threadIdx.x;
    if (i < N_NODES) g_deg[i] = 0;
    if (blockIdx.x == 0) {
        const int* w = (const int*)srcbuf;
        __shared__ int odd_nz;
        if (threadIdx.x == 0) odd_nz = 0;
        __syncthreads();
        int bad = 0;
        for (int k = threadIdx.x; k < 1024; k += blockDim.x)
            if (w[2 * k + 1] != 0) bad = 1;       // stays within 8KB of buffer
        if (bad) atomicOr(&odd_nz, 1);
        __syncthreads();
        if (threadIdx.x == 0) g_i64 = (odd_nz == 0) ? 1 : 0;
    }
}

__device__ __forceinline__ int idx_at(const void* p, int e, int i64) {
    return i64 ? (int)((const long long*)p)[e] : ((const int*)p)[e];
}

// -------------------- conversions -------------------------------------------
__global__ void k_xtoh(const float* __restrict__ x) {
    int i = blockIdx.x * blockDim.x + threadIdx.x;   // one float4 per thread
    if (i < N_NODES * D_IN / 4) {
        float4 v = ((const float4*)x)[i];
        __half2 a = __floats2half2_rn(v.x, v.y);
        __half2 b = __floats2half2_rn(v.z, v.w);
        uint2 u;
        u.x = *reinterpret_cast<unsigned*>(&a);
        u.y = *reinterpret_cast<unsigned*>(&b);
        ((uint2*)g_xh)[i] = u;
    }
}

// weights -> fp16 scratch.  B1 = [Ws1 ; Wn1] (256 k-rows of 128),
// B2[k][n] = n<64 ? Ws2[k][n] : Wn2[k][n-64]
__global__ void k_wtoh(const float* __restrict__ Ws1,
                       const float* __restrict__ Wn1,
                       const float* __restrict__ Ws2,
                       const float* __restrict__ Wn2) {
    int i = blockIdx.x * blockDim.x + threadIdx.x;
    if (i < 16384) {
        g_B1h[i] = __float2half_rn(Ws1[i]);
    } else if (i < 32768) {
        g_B1h[i] = __float2half_rn(Wn1[i - 16384]);
    } else if (i < 49152) {
        int t = i - 32768;
        int k = t >> 7, n = t & 127;
        float v = (n < 64) ? Ws2[k * 64 + n] : Wn2[k * 64 + (n - 64)];
        g_B2h[t] = __float2half_rn(v);
    }
}

// -------------------- CSR build ---------------------------------------------
__global__ void k_hist(const void* dst) {
    int e = blockIdx.x * blockDim.x + threadIdx.x;
    int i64 = g_i64;
    if (e < N_EDGES) {
        int d = idx_at(dst, e, i64);
        if (d >= 0 && d < N_NODES) atomicAdd(&g_deg[d], 1);
    }
}

__global__ __launch_bounds__(128) void k_scan_partial() {
    __shared__ int s[128];
    int t = threadIdx.x;
    int i = blockIdx.x * 128 + t;
    int d = (i < N_NODES) ? g_deg[i] : 0;
    s[t] = d;
    __syncthreads();
#pragma unroll
    for (int off = 1; off < 128; off <<= 1) {
        int v = (t >= off) ? s[t - off] : 0;
        __syncthreads();
        s[t] += v;
        __syncthreads();
    }
    if (t == 127) g_bsum[blockIdx.x] = s[127];
}

__global__ __launch_bounds__(1024) void k_scan_tops() {
    __shared__ int s[1024];
    int t = threadIdx.x;
    int v0 = (t < SCAN_NB) ? g_bsum[t] : 0;
    s[t] = v0;
    __syncthreads();
#pragma unroll
    for (int off = 1; off < 1024; off <<= 1) {
        int v = (t >= off) ? s[t - off] : 0;
        __syncthreads();
        s[t] += v;
        __syncthreads();
    }
    if (t < SCAN_NB) g_boff[t] = s[t] - v0;        // exclusive
    if (t == 1023) g_rowptr[N_NODES] = s[1023];    // grand total
}

__global__ __launch_bounds__(128) void k_scan_fill() {
    __shared__ int s[128];
    int t = threadIdx.x;
    int i = blockIdx.x * 128 + t;
    int d = (i < N_NODES) ? g_deg[i] : 0;
    s[t] = d;
    __syncthreads();
#pragma unroll
    for (int off = 1; off < 128; off <<= 1) {
        int v = (t >= off) ? s[t - off] : 0;
        __syncthreads();
        s[t] += v;
        __syncthreads();
    }
    if (i < N_NODES) {
        int p = g_boff[blockIdx.x] + s[t] - d;     // exclusive prefix
        g_rowptr[i] = p;
        g_cursor[i] = p;
    }
}

__global__ void k_scatter(const void* src, const void* dst) {
    int e = blockIdx.x * blockDim.x + threadIdx.x;
    int i64 = g_i64;
    if (e < N_EDGES) {
        int d = idx_at(dst, e, i64);
        int s = idx_at(src, e, i64);
        if (d >= 0 && d < N_NODES && s >= 0 && s < N_NODES) {
            int pos = atomicAdd(&g_cursor[d], 1);
            g_csrsrc[pos] = s;
        }
    }
}

// -------------------- aggregation kernels (fp16 payload, fp32 accum) --------
// layer 1: one warp per node; row = 128 halfs = 32 uint2 lanes (8B/lane)
// writes fp16 g_aggh (GEMM A-input), fp32 accumulation inside.
__global__ void k_agg128h() {
    int gtid = blockIdx.x * blockDim.x + threadIdx.x;
    int node = gtid >> 5;
    int lane = gtid & 31;
    if (node >= N_NODES) return;
    int beg = g_rowptr[node];
    int end = g_rowptr[node + 1];
    const uint2* xh = (const uint2*)g_xh;
    float ax0 = 0.f, ay0 = 0.f, az0 = 0.f, aw0 = 0.f;
    float ax1 = 0.f, ay1 = 0.f, az1 = 0.f, aw1 = 0.f;
    int j = beg;
    for (; j + 1 < end; j += 2) {
        int s0 = g_csrsrc[j];
        int s1 = g_csrsrc[j + 1];
        uint2 u0 = xh[(size_t)s0 * 32 + lane];
        uint2 u1 = xh[(size_t)s1 * 32 + lane];
        float2 l0 = __half22float2(*reinterpret_cast<__half2*>(&u0.x));
        float2 h0 = __half22float2(*reinterpret_cast<__half2*>(&u0.y));
        float2 l1 = __half22float2(*reinterpret_cast<__half2*>(&u1.x));
        float2 h1 = __half22float2(*reinterpret_cast<__half2*>(&u1.y));
        ax0 += l0.x; ay0 += l0.y; az0 += h0.x; aw0 += h0.y;
        ax1 += l1.x; ay1 += l1.y; az1 += h1.x; aw1 += h1.y;
    }
    if (j < end) {
        int s0 = g_csrsrc[j];
        uint2 u0 = xh[(size_t)s0 * 32 + lane];
        float2 l0 = __half22float2(*reinterpret_cast<__half2*>(&u0.x));
        float2 h0 = __half22float2(*reinterpret_cast<__half2*>(&u0.y));
        ax0 += l0.x; ay0 += l0.y; az0 += h0.x; aw0 += h0.y;
    }
    int deg = end - beg;
    float inv = 1.0f / (float)(deg > 0 ? deg : 1);
    __half2 p0 = __floats2half2_rn((ax0 + ax1) * inv, (ay0 + ay1) * inv);
    __half2 p1 = __floats2half2_rn((az0 + az1) * inv, (aw0 + aw1) * inv);
    uint2 u;
    u.x = *reinterpret_cast<unsigned*>(&p0);
    u.y = *reinterpret_cast<unsigned*>(&p1);
    ((uint2*)g_aggh)[(size_t)node * 32 + lane] = u;
}

// layer 2: one warp per node over g_th; row = 64 halfs = 32 half2 lanes
__global__ void k_agg64h(float* __restrict__ out) {
    int gtid = blockIdx.x * blockDim.x + threadIdx.x;
    int node = gtid >> 5;
    int lane = gtid & 31;
    if (node >= N_NODES) return;
    int beg = g_rowptr[node];
    int end = g_rowptr[node + 1];
    const __half2* th = (const __half2*)g_th;
    float ax0 = 0.f, ay0 = 0.f, ax1 = 0.f, ay1 = 0.f;
    int j = beg;
    for (; j + 1 < end; j += 2) {
        int s0 = g_csrsrc[j];
        int s1 = g_csrsrc[j + 1];
        float2 v0 = __half22float2(th[(size_t)s0 * 32 + lane]);
        float2 v1 = __half22float2(th[(size_t)s1 * 32 + lane]);
        ax0 += v0.x; ay0 += v0.y;
        ax1 += v1.x; ay1 += v1.y;
    }
    if (j < end) {
        int s0 = g_csrsrc[j];
        float2 v0 = __half22float2(th[(size_t)s0 * 32 + lane]);
        ax0 += v0.x; ay0 += v0.y;
    }
    int deg = end - beg;
    float inv = 1.0f / (float)(deg > 0 ? deg : 1);
    float2* o2 = (float2*)out;
    float2 cur = o2[(size_t)node * 32 + lane];
    cur.x += (ax0 + ax1) * inv;
    cur.y += (ay0 + ay1) * inv;
    o2[(size_t)node * 32 + lane] = cur;
}

// -------------------- wmma tensor-core GEMMs --------------------------------
// Block: 256 threads = 8 warps, 4 (M) x 2 (N); each warp does 32x64 via
// 2x4 fragments of 16x16x16 (fp16 in, fp32 acc).  BM=128, BN=128.

// g_hh = relu( [g_xh | g_aggh] @ g_B1h + b1 )  : K = 256
__global__ __launch_bounds__(256) void k_gemm1h(const float* __restrict__ b1) {
    __shared__ __align__(16) __half As[128][16];
    __shared__ __align__(16) __half Bs[16][128];
    __shared__ __align__(16) float  Cst[8][256];
    const int tid = threadIdx.x;
    const int warp = tid >> 5;
    const int lane = tid & 31;
    const int warpM = warp & 3;   // 0..3
    const int warpN = warp >> 2;  // 0..1
    const int rowBase = blockIdx.x * 128;

    wmma::fragment<wmma::accumulator, 16, 16, 16, float> acc[2][4];
#pragma unroll
    for (int i = 0; i < 2; i++)
#pragma unroll
        for (int j = 0; j < 4; j++) wmma::fill_fragment(acc[i][j], 0.f);

    const int aRow = tid >> 1;          // 0..127
    const int aCol8 = (tid & 1) * 8;    // 0 / 8
    int arow_g = rowBase + aRow;
    if (arow_g >= N_NODES) arow_g = N_NODES - 1;
    const int bRow = tid >> 4;          // 0..15
    const int bCol8 = (tid & 15) * 8;   // 0..120

    for (int kk = 0; kk < 16; kk++) {
        const __half* Ap = (kk < 8)
            ? (g_xh   + (size_t)arow_g * 128 + kk * 16 + aCol8)
            : (g_aggh + (size_t)arow_g * 128 + (kk - 8) * 16 + aCol8);
        uint4 av = *(const uint4*)Ap;
        uint4 bv = *(const uint4*)(g_B1h + (size_t)(kk * 16 + bRow) * 128 + bCol8);
        __syncthreads();
        *(uint4*)&As[aRow][aCol8] = av;
        *(uint4*)&Bs[bRow][bCol8] = bv;
        __syncthreads();

        wmma::fragment<wmma::matrix_b, 16, 16, 16, __half, wmma::row_major> bf[4];
#pragma unroll
        for (int j = 0; j < 4; j++)
            wmma::load_matrix_sync(bf[j], &Bs[0][warpN * 64 + j * 16], 128);
#pragma unroll
        for (int i = 0; i < 2; i++) {
            wmma::fragment<wmma::matrix_a, 16, 16, 16, __half, wmma::row_major> af;
            wmma::load_matrix_sync(af, &As[warpM * 32 + i * 16][0], 16);
#pragma unroll
            for (int j = 0; j < 4; j++)
                wmma::mma_sync(acc[i][j], af, bf[j], acc[i][j]);
        }
    }

    // epilogue: bias + relu -> fp16 g_hh
#pragma unroll
    for (int i = 0; i < 2; i++)
#pragma unroll
        for (int j = 0; j < 4; j++) {
            __syncwarp();
            wmma::store_matrix_sync(&Cst[warp][0], acc[i][j], 16, wmma::mem_row_major);
            __syncwarp();
            int r = rowBase + warpM * 32 + i * 16 + (lane >> 1);
            int c = warpN * 64 + j * 16 + (lane & 1) * 8;
            if (r < N_NODES) {
                const float* row = &Cst[warp][(lane >> 1) * 16 + (lane & 1) * 8];
                float v[8];
#pragma unroll
                for (int q = 0; q < 8; q++) {
                    float z = row[q] + b1[c + q];
                    v[q] = z > 0.f ? z : 0.f;
                }
                __half2 p0 = __floats2half2_rn(v[0], v[1]);
                __half2 p1 = __floats2half2_rn(v[2], v[3]);
                __half2 p2 = __floats2half2_rn(v[4], v[5]);
                __half2 p3 = __floats2half2_rn(v[6], v[7]);
                uint4 u;
                u.x = *reinterpret_cast<unsigned*>(&p0);
                u.y = *reinterpret_cast<unsigned*>(&p1);
                u.z = *reinterpret_cast<unsigned*>(&p2);
                u.w = *reinterpret_cast<unsigned*>(&p3);
                *(uint4*)(g_hh + (size_t)r * 128 + c) = u;
            }
        }
}

// [self | neigh] = g_hh @ g_B2h : K = 128.
// warpN==0 (cols 0..63, self): +b2 -> out fp32.  warpN==1: -> g_th fp16.
__global__ __launch_bounds__(256) void k_gemm2h(const float* __restrict__ b2,
                                                float* __restrict__ out) {
    __shared__ __align__(16) __half As[128][16];
    __shared__ __align__(16) __half Bs[16][128];
    __shared__ __align__(16) float  Cst[8][256];
    const int tid = threadIdx.x;
    const int warp = tid >> 5;
    const int lane = tid & 31;
    const int warpM = warp & 3;
    const int warpN = warp >> 2;
    const int rowBase = blockIdx.x * 128;

    wmma::fragment<wmma::accumulator, 16, 16, 16, float> acc[2][4];
#pragma unroll
    for (int i = 0; i < 2; i++)
#pragma unroll
        for (int j = 0; j < 4; j++) wmma::fill_fragment(acc[i][j], 0.f);

    const int aRow = tid >> 1;
    const int aCol8 = (tid & 1) * 8;
    int arow_g = rowBase + aRow;
    if (arow_g >= N_NODES) arow_g = N_NODES - 1;
    const int bRow = tid >> 4;
    const int bCol8 = (tid & 15) * 8;

    for (int kk = 0; kk < 8; kk++) {
        uint4 av = *(const uint4*)(g_hh + (size_t)arow_g * 128 + kk * 16 + aCol8);
        uint4 bv = *(const uint4*)(g_B2h + (size_t)(kk * 16 + bRow) * 128 + bCol8);
        __syncthreads();
        *(uint4*)&As[aRow][aCol8] = av;
        *(uint4*)&Bs[bRow][bCol8] = bv;
        __syncthreads();

        wmma::fragment<wmma::matrix_b, 16, 16, 16, __half, wmma::row_major> bf[4];
#pragma unroll
        for (int j = 0; j < 4; j++)
            wmma::load_matrix_sync(bf[j], &Bs[0][warpN * 64 + j * 16], 128);
#pragma unroll
        for (int i = 0; i < 2; i++) {
            wmma::fragment<wmma::matrix_a, 16, 16, 16, __half, wmma::row_major> af;
            wmma::load_matrix_sync(af, &As[warpM * 32 + i * 16][0], 16);
#pragma unroll
            for (int j = 0; j < 4; j++)
                wmma::mma_sync(acc[i][j], af, bf[j], acc[i][j]);
        }
    }

#pragma unroll
    for (int i = 0; i < 2; i++)
#pragma unroll
        for (int j = 0; j < 4; j++) {
            __syncwarp();
            wmma::store_matrix_sync(&Cst[warp][0], acc[i][j], 16, wmma::mem_row_major);
            __syncwarp();
            int r = rowBase + warpM * 32 + i * 16 + (lane >> 1);
            int cc = j * 16 + (lane & 1) * 8;     // 0..63 within half
            if (r < N_NODES) {
                const float* row = &Cst[warp][(lane >> 1) * 16 + (lane & 1) * 8];
                if (warpN == 0) {                 // self half -> fp32 out
                    float v[8];
#pragma unroll
                    for (int q = 0; q < 8; q++) v[q] = row[q] + b2[cc + q];
                    float4* dst4 = (float4*)(out + (size_t)r * D_OUT + cc);
                    dst4[0] = make_float4(v[0], v[1], v[2], v[3]);
                    dst4[1] = make_float4(v[4], v[5], v[6], v[7]);
                } else {                          // neigh half -> fp16 g_th
                    __half2 p0 = __floats2half2_rn(row[0], row[1]);
                    __half2 p1 = __floats2half2_rn(row[2], row[3]);
                    __half2 p2 = __floats2half2_rn(row[4], row[5]);
                    __half2 p3 = __floats2half2_rn(row[6], row[7]);
                    uint4 u;
                    u.x = *reinterpret_cast<unsigned*>(&p0);
                    u.y = *reinterpret_cast<unsigned*>(&p1);
                    u.z = *reinterpret_cast<unsigned*>(&p2);
                    u.w = *reinterpret_cast<unsigned*>(&p3);
                    *(uint4*)(g_th + (size_t)r * D_OUT + cc) = u;
                }
            }
        }
}

// ---------------------------------------------------------------------------
extern "C" void kernel_launch(void* const* d_in, const int* in_sizes, int n_in,
                              void* d_out, int out_size) {
    const float* x   = (const float*)d_in[0];
    const void*  src = d_in[1];
    const void*  dst = d_in[2];
    const float* Ws1 = (const float*)d_in[3];
    const float* Wn1 = (const float*)d_in[4];
    const float* b1  = (const float*)d_in[5];
    const float* Ws2 = (const float*)d_in[6];
    const float* Wn2 = (const float*)d_in[7];
    const float* b2  = (const float*)d_in[8];
    float* out = (float*)d_out;

    // 1) CSR build (scatter lands at ncu -s 5 capture slot)
    k_detect_zero<<<(N_NODES + 255) / 256, 256>>>(src);
    k_hist<<<(N_EDGES + 255) / 256, 256>>>(dst);
    k_scan_partial<<<SCAN_NB, 128>>>();
    k_scan_tops<<<1, 1024>>>();
    k_scan_fill<<<SCAN_NB, 128>>>();
    k_scatter<<<(N_EDGES + 255) / 256, 256>>>(src, dst);

    // 2) fp16 conversions (x + weights)
    k_xtoh<<<(N_NODES * D_IN / 4 + 255) / 256, 256>>>(x);
    k_wtoh<<<(49152 + 255) / 256, 256>>>(Ws1, Wn1, Ws2, Wn2);

    // 3) layer 1
    k_agg128h<<<(N_NODES * 32 + 255) / 256, 256>>>();
    k_gemm1h<<<(N_NODES + 127) / 128, 256>>>(b1);

    // 4) layer 2 (transform first, aggregate fp16 64-wide afterwards)
    k_gemm2h<<<(N_NODES + 127) / 128, 256>>>(b2, out);
    k_agg64h<<<(N_NODES * 32 + 255) / 256, 256>>>(out);
}